// round 15
// baseline (speedup 1.0000x reference)
#include <cuda_runtime.h>
#include <cuda_fp16.h>

#define HH 200
#define WW 320
#define CC 256
#define HWSZ (HH * WW)
#define RS 14
#define BINS (RS * RS)
#define NSTRIP (HWSZ / 32)   // 2000
#define NTBLK (NSTRIP * 4)   // 8000 transpose blocks (4 channel blocks/strip)

// featT [H*W][C] fp16. g_bins: per-bin maxima (encoded; 0 acts as -inf
// sentinel, reset to 0 by bid 0 each launch, gated by g_init).
// g_strip/g_init: producer-consumer flags; invariant "0 at launch start"
// (zero-init statics on first run; bcast resets them each launch).
__device__ __align__(128) static __half g_featT[(size_t)HWSZ * CC];
__device__ static unsigned g_bins[BINS];
__device__ static unsigned g_strip[NSTRIP];
__device__ static unsigned g_init;

// Monotonic float -> uint encoding; every real float encodes > 0, so 0 is a
// valid "-inf" sentinel for atomicMax.
__device__ __forceinline__ unsigned enc_f(float f) {
    unsigned u = __float_as_uint(f);
    return (u & 0x80000000u) ? ~u : (u | 0x80000000u);
}
__device__ __forceinline__ float dec_f(unsigned u) {
    return __uint_as_float((u & 0x80000000u) ? (u ^ 0x80000000u) : ~u);
}

// Fused producer/consumer kernel.
//  bid < NTBLK: transpose one 64ch x 32hw tile (R12 scheme: half2 convert at
//    load, [32][33] uint smem tile, one STG.128/thread), then signal its strip.
//    bid&3 = channel block, bid>>2 = strip -> strips complete progressively.
//  bid >= NTBLK: roi consumer block = (roi, m, half): 7 warps, warp = bin n.
//    Waits only for the <=16 corner-pixel strips it needs, then runs the
//    champion sample loop and one gated atomicMax.
__global__ void fused_kernel(const float* __restrict__ A,
                             const float* __restrict__ rois, int R) {
    int bid = blockIdx.x;
    int t = threadIdx.x;

    if (bid < NTBLK) {
        __shared__ unsigned sm[32][33];  // sm[hw][c_pair]
        int bx = bid >> 2;               // strip
        int by = bid & 3;                // channel block
        int hw0 = bx * 32;
        int c0 = by * 64;
        int tx = t & 31, ty = t >> 5;    // 32 x 8

        if (bid == 0 && t < BINS) g_bins[t] = 0u;  // sentinel reset (gated by g_init)

#pragma unroll
        for (int j = 0; j < 4; j++) {
            int cIdx = ty * 8 + j * 2;
            const float* p = A + (size_t)(c0 + cIdx) * HWSZ + hw0 + tx;
            float f0 = p[0];
            float f1 = p[HWSZ];
            __half2 h = __floats2half2_rn(f0, f1);
            sm[tx][cIdx >> 1] = *(unsigned*)&h;
        }
        __syncthreads();

        int hw = ty * 4 + (tx >> 3);
        int col8 = tx & 7;
        uint4 v = make_uint4(sm[hw][4 * col8 + 0], sm[hw][4 * col8 + 1],
                             sm[hw][4 * col8 + 2], sm[hw][4 * col8 + 3]);
        *(uint4*)(g_featT + (size_t)(hw0 + hw) * CC + c0 + 8 * col8) = v;

        __syncthreads();
        if (t == 0) {
            __threadfence();             // publish tile (and bid0's g_bins reset)
            atomicAdd(&g_strip[bx], 1u);
            if (bid == 0) atomicExch(&g_init, 1u);
        }
        return;
    }

    // ---- roi consumer ----
    int b = bid - NTBLK;
    int half = b & 1;
    int rm = b >> 1;
    int r = rm / RS;
    int m = rm - r * RS;
    int w = t >> 5;
    int lane = t & 31;
    if (w >= 7) return;
    int n = half * 7 + w;
    int mn = m * RS + n;

    float r0 = __ldg(rois + 4 * r + 0);
    float r1 = __ldg(rois + 4 * r + 1);
    float r2 = __ldg(rois + 4 * r + 2);
    float r3 = __ldg(rois + 4 * r + 3);
    float sh = (r2 - r0) / (float)RS;
    float sw = (r3 - r1) / (float)RS;
    float yb = r0 + sh * (float)m;
    float xb = r1 + sw * (float)n;
    const float fr0 = 1.0f / 3.0f, fr1 = 2.0f / 3.0f;
    float ys[2] = {yb + sh * fr0, yb + sh * fr1};
    float xs[2] = {xb + sw * fr0, xb + sw * fr1};

    // Corner rows/cols (clamped exactly like the main loop).
    int rows[4], cols[4];
#pragma unroll
    for (int i = 0; i < 2; i++) {
        int yf = (int)floorf(ys[i]);
        rows[2 * i] = min(max(yf, 0), HH - 1);
        rows[2 * i + 1] = min(max(yf + 1, 0), HH - 1);
        int xf = (int)floorf(xs[i]);
        cols[2 * i] = min(max(xf, 0), WW - 1);
        cols[2 * i + 1] = min(max(xf + 1, 0), WW - 1);
    }
    // Lanes 0..15 each guard one corner pixel's strip.
    int sidx = 0;
    bool pend = (lane < 16);
    if (pend) sidx = (rows[lane >> 2] * WW + cols[lane & 3]) >> 5;
    while (__any_sync(0xffffffffu, pend)) {
        if (pend) pend = (__ldcv(&g_strip[sidx]) < 4u);
    }
    __threadfence();  // acquire: order featT reads after observed strip counts

    float vmax = __int_as_float(0xff800000);  // -inf

#pragma unroll
    for (int i = 0; i < 2; i++) {
#pragma unroll
        for (int j = 0; j < 2; j++) {
            float y = ys[i], x = xs[j];
            int yf = (int)floorf(y);
            int xf = (int)floorf(x);
            int y1 = min(max(yf, 0), HH - 1);
            int y2 = min(max(yf + 1, 0), HH - 1);
            int x1 = min(max(xf, 0), WW - 1);
            int x2 = min(max(xf + 1, 0), WW - 1);
            float wxl = x - (float)x1;
            float wxh = (float)x2 - x;
            float wyl = y - (float)y1;
            float wyh = (float)y2 - y;

            const uint4* p11 = (const uint4*)(g_featT + (size_t)(y1 * WW + x1) * CC);
            const uint4* p12 = (const uint4*)(g_featT + (size_t)(y1 * WW + x2) * CC);
            const uint4* p21 = (const uint4*)(g_featT + (size_t)(y2 * WW + x1) * CC);
            const uint4* p22 = (const uint4*)(g_featT + (size_t)(y2 * WW + x2) * CC);

            uint4 Av = p11[lane];
            uint4 Bv = p12[lane];
            uint4 Cv = p21[lane];
            uint4 Dv = p22[lane];
#pragma unroll
            for (int k = 0; k < 4; k++) {
                float2 fa = __half22float2(*(const __half2*)(&((const unsigned*)&Av)[k]));
                float2 fb = __half22float2(*(const __half2*)(&((const unsigned*)&Bv)[k]));
                float2 fc = __half22float2(*(const __half2*)(&((const unsigned*)&Cv)[k]));
                float2 fd = __half22float2(*(const __half2*)(&((const unsigned*)&Dv)[k]));
                float v0 = (fa.x * wxh + fb.x * wxl) * wyh + (fc.x * wxh + fd.x * wxl) * wyl;
                float v1 = (fa.y * wxh + fb.y * wxl) * wyh + (fc.y * wxh + fd.y * wxl) * wyl;
                vmax = fmaxf(vmax, fmaxf(v0, v1));
            }
        }
    }

#pragma unroll
    for (int o = 16; o; o >>= 1)
        vmax = fmaxf(vmax, __shfl_xor_sync(0xffffffffu, vmax, o));
    if (lane == 0) {
        while (__ldcv(&g_init) == 0u) {}  // bid0's g_bins reset published
        __threadfence();
        atomicMax(&g_bins[mn], enc_f(vmax));
    }
}

// Broadcast bin_max to out[R][C][14][14] (4 warp-contiguous float4 stores per
// thread; bin index advances by 11 mod 49). Also restores the flag invariants
// for the next graph replay (runs strictly after fused_kernel).
__global__ void bcast_kernel(float* __restrict__ out, int total4) {
    __shared__ float4 s4[49];
    int t = threadIdx.x;
    if (t < BINS) ((float*)s4)[t] = dec_f(g_bins[t]);
    __syncthreads();

    int gi = blockIdx.x * 256 + t;
    if (gi < NSTRIP) g_strip[gi] = 0u;
    if (gi == NSTRIP) g_init = 0u;

    int g0 = blockIdx.x * 1024 + t;
    int mq = g0 % 49;
#pragma unroll
    for (int k = 0; k < 4; k++) {
        int g = g0 + k * 256;
        if (g < total4) ((float4*)out)[g] = s4[mq];
        mq += 11;
        if (mq >= 49) mq -= 49;
    }
}

extern "C" void kernel_launch(void* const* d_in, const int* in_sizes, int n_in,
                              void* d_out, int out_size) {
    const float* feature = (const float*)d_in[0];
    const float* rois = (const float*)d_in[1];
    int R = in_sizes[1] / 4;

    int nroi_blocks = 2 * R * RS;
    fused_kernel<<<NTBLK + nroi_blocks, 256>>>(feature, rois, R);

    int total4 = out_size / 4;
    bcast_kernel<<<(total4 + 1023) / 1024, 256>>>((float*)d_out, total4);
}

// round 16
// speedup vs baseline: 1.0375x; 1.0375x over previous
#include <cuda_runtime.h>
#include <cuda_fp16.h>

#define HH 200
#define WW 320
#define CC 256
#define HWSZ (HH * WW)
#define RS 14
#define BINS (RS * RS)

// Scratch: transposed feature [H*W][C] fp16 (32.8 MB) + 196 bin maxima
__device__ __align__(128) static __half g_featT[(size_t)HWSZ * CC];
__device__ static unsigned g_bins[BINS];

// Monotonic float <-> uint encoding so atomicMax on unsigned == float max
__device__ __forceinline__ unsigned enc_f(float f) {
    unsigned u = __float_as_uint(f);
    return (u & 0x80000000u) ? ~u : (u | 0x80000000u);
}
__device__ __forceinline__ float dec_f(unsigned u) {
    return __uint_as_float((u & 0x80000000u) ? (u ^ 0x80000000u) : ~u);
}
#define ENC_NEG_INF 0x007FFFFFu  // enc_f(-inf)

// Transpose feature [C][H*W] fp32 -> g_featT [H*W][C] fp16 (R12/R13 version:
// half2 conversion at load, 4 STS.32 into [32][33] uint tile, one
// STG.128/thread in phase 2). Block (0,0) initializes g_bins.
__global__ void transpose_kernel(const float* __restrict__ A) {
    __shared__ unsigned sm[32][33];  // sm[hw][c_pair] = half2(c, c+1)
    int hw0 = blockIdx.x * 32;
    int c0 = blockIdx.y * 64;
    int tx = threadIdx.x, ty = threadIdx.y;  // 32 x 8

    if (blockIdx.x == 0 && blockIdx.y == 0) {
        int t = ty * 32 + tx;
        if (t < BINS) g_bins[t] = ENC_NEG_INF;
    }

#pragma unroll
    for (int j = 0; j < 4; j++) {
        int cIdx = ty * 8 + j * 2;
        const float* p = A + (size_t)(c0 + cIdx) * HWSZ + hw0 + tx;
        float f0 = p[0];
        float f1 = p[HWSZ];
        __half2 h = __floats2half2_rn(f0, f1);
        sm[tx][cIdx >> 1] = *(unsigned*)&h;
    }
    __syncthreads();

    int hw = ty * 4 + (tx >> 3);
    int col8 = tx & 7;
    uint4 v = make_uint4(sm[hw][4 * col8 + 0], sm[hw][4 * col8 + 1],
                         sm[hw][4 * col8 + 2], sm[hw][4 * col8 + 3]);
    *(uint4*)(g_featT + (size_t)(hw0 + hw) * CC + c0 + 8 * col8) = v;
}

// Block = one (roi, m-row): 14 warps, warp = bin n (R13 mapping, keeps
// cross-warp L1 sharing). NEW: within a warp, the 16 corner pixels of the 4
// sample points collapse to dy*dx distinct ones (dy,dx in {2,3,4}; ~9 avg).
// All coords are warp-uniform -> dedupe with UNIFORM branches, loading each
// distinct pixel once and accumulating it into all 4 sample accumulators with
// weight wy_i * wx_j (expanded bilinear; clamp-duplicates fold in exactly).
__global__ void roi_max_kernel(const float* __restrict__ rois) {
    int lane = threadIdx.x & 31;
    int n = threadIdx.x >> 5;        // 0..13
    int r = blockIdx.x / RS;
    int m = blockIdx.x - r * RS;
    int mn = m * RS + n;

    float r0 = __ldg(rois + 4 * r + 0);
    float r1 = __ldg(rois + 4 * r + 1);
    float r2 = __ldg(rois + 4 * r + 2);
    float r3 = __ldg(rois + 4 * r + 3);
    float sh = (r2 - r0) / (float)RS;
    float sw = (r3 - r1) / (float)RS;
    float yb = r0 + sh * (float)m;
    float xb = r1 + sw * (float)n;
    const float fr0 = 1.0f / 3.0f, fr1 = 2.0f / 3.0f;
    float ys[2] = {yb + sh * fr0, yb + sh * fr1};
    float xs[2] = {xb + sw * fr0, xb + sw * fr1};

    // Clamp corner indices BEFORE weights (faithful to reference).
    int y1[2], y2[2], x1[2], x2[2];
    float wyh[2], wyl[2], wxh[2], wxl[2];
#pragma unroll
    for (int i = 0; i < 2; i++) {
        int yf = (int)floorf(ys[i]);
        y1[i] = min(max(yf, 0), HH - 1);
        y2[i] = min(max(yf + 1, 0), HH - 1);
        wyl[i] = ys[i] - (float)y1[i];
        wyh[i] = (float)y2[i] - ys[i];
        int xf = (int)floorf(xs[i]);
        x1[i] = min(max(xf, 0), WW - 1);
        x2[i] = min(max(xf + 1, 0), WW - 1);
        wxl[i] = xs[i] - (float)x1[i];
        wxh[i] = (float)x2[i] - xs[i];
    }

    int ycand[4] = {y1[0], y2[0], y1[1], y2[1]};
    int xcand[4] = {x1[0], x2[0], x1[1], x2[1]};

    // acc[s][k]: sample s = 2*i + j, chunk k = half2 pair of channels.
    float2 acc[4][4];
#pragma unroll
    for (int s = 0; s < 4; s++)
#pragma unroll
        for (int k = 0; k < 4; k++) acc[s][k] = make_float2(0.f, 0.f);

#pragma unroll
    for (int a = 0; a < 4; a++) {
        int ry = ycand[a];
        bool dup = false;
#pragma unroll
        for (int b = 0; b < 4; b++)
            if (b < a && ycand[b] == ry) dup = true;
        if (dup) continue;  // warp-uniform
        float wy0 = (ry == y1[0] ? wyh[0] : 0.f) + (ry == y2[0] ? wyl[0] : 0.f);
        float wy1 = (ry == y1[1] ? wyh[1] : 0.f) + (ry == y2[1] ? wyl[1] : 0.f);

#pragma unroll
        for (int c = 0; c < 4; c++) {
            int cx = xcand[c];
            bool dupx = false;
#pragma unroll
            for (int b = 0; b < 4; b++)
                if (b < c && xcand[b] == cx) dupx = true;
            if (dupx) continue;  // warp-uniform
            float wx0 = (cx == x1[0] ? wxh[0] : 0.f) + (cx == x2[0] ? wxl[0] : 0.f);
            float wx1 = (cx == x1[1] ? wxh[1] : 0.f) + (cx == x2[1] ? wxl[1] : 0.f);
            float w00 = wy0 * wx0, w01 = wy0 * wx1;
            float w10 = wy1 * wx0, w11 = wy1 * wx1;

            const uint4* p = (const uint4*)(g_featT + (size_t)(ry * WW + cx) * CC);
            uint4 V = p[lane];
#pragma unroll
            for (int k = 0; k < 4; k++) {
                float2 f = __half22float2(*(const __half2*)(&((const unsigned*)&V)[k]));
                acc[0][k].x += w00 * f.x; acc[0][k].y += w00 * f.y;
                acc[1][k].x += w01 * f.x; acc[1][k].y += w01 * f.y;
                acc[2][k].x += w10 * f.x; acc[2][k].y += w10 * f.y;
                acc[3][k].x += w11 * f.x; acc[3][k].y += w11 * f.y;
            }
        }
    }

    float vmax = __int_as_float(0xff800000);  // -inf
#pragma unroll
    for (int s = 0; s < 4; s++)
#pragma unroll
        for (int k = 0; k < 4; k++)
            vmax = fmaxf(vmax, fmaxf(acc[s][k].x, acc[s][k].y));

#pragma unroll
    for (int o = 16; o; o >>= 1)
        vmax = fmaxf(vmax, __shfl_xor_sync(0xffffffffu, vmax, o));
    if (lane == 0) atomicMax(&g_bins[mn], enc_f(vmax));
}

// Broadcast bin_max to out[R][C][14][14]. Each thread does 4 warp-contiguous
// float4 stores; bin index advances by 11 mod 49 per store (256 mod 49 == 11).
__global__ void bcast_kernel(float* __restrict__ out, int total4) {
    __shared__ float4 s4[49];
    int t = threadIdx.x;
    if (t < BINS) ((float*)s4)[t] = dec_f(g_bins[t]);
    __syncthreads();
    int g0 = blockIdx.x * 1024 + t;
    int mq = g0 % 49;
#pragma unroll
    for (int k = 0; k < 4; k++) {
        int g = g0 + k * 256;
        if (g < total4) ((float4*)out)[g] = s4[mq];
        mq += 11;
        if (mq >= 49) mq -= 49;
    }
}

extern "C" void kernel_launch(void* const* d_in, const int* in_sizes, int n_in,
                              void* d_out, int out_size) {
    const float* feature = (const float*)d_in[0];
    const float* rois = (const float*)d_in[1];
    int R = in_sizes[1] / 4;

    dim3 tb(32, 8);
    dim3 tg(HWSZ / 32, CC / 64);
    transpose_kernel<<<tg, tb>>>(feature);

    roi_max_kernel<<<R * RS, RS * 32>>>(rois);

    int total4 = out_size / 4;
    bcast_kernel<<<(total4 + 1023) / 1024, 256>>>((float*)d_out, total4);
}